// round 13
// baseline (speedup 1.0000x reference)
#include <cuda_runtime.h>
#include <cuda_fp16.h>
#include <cstdint>
#include <math.h>

// ============================================================================
// BinaryLinear: y[8192,4096] = x[8192,4096] @ (aa*tanh(kk*W))^T + bias
// fp16 mma.sync.m16n8k16 register GEMM (fp32 acc), ldmatrix.x4, frag dbl-buffer.
// CTA 128x128, 4 warps (2x2), warp tile 64x64, 3-stage cp.async, TK=64 halves.
// 2 CTAs/SM; SW128 swizzle; stage-pointer rotation.
// R13: kq0 peeled -> gmem burst issues AFTER the first MMA group (short head);
//      prep_w uses tanh.approx.f32.
// ============================================================================

#define MDIM 8192
#define NDIM 4096
#define KDIM 4096

#define TM 128
#define TN 128
#define TK 64                          // halves per stage-row (128B)
#define NSTAGES 3
#define KITERS (KDIM / TK)             // 64

#define A_STAGE_BYTES (TM * TK * 2)    // 16384
#define B_STAGE_BYTES (TN * TK * 2)    // 16384
#define STAGE_BYTES (A_STAGE_BYTES + B_STAGE_BYTES)     // 32768
#define SMEM_BYTES (NSTAGES * STAGE_BYTES)              // 98304

#define W_PREP_BLOCKS (NDIM * KDIM / 4096)   // 4096 (16 elems/thread)
#define X_PREP_BLOCKS (MDIM * KDIM / 4096)   // 8192

// fp16 operands (persistent scratch)
__device__ __half g_wh[NDIM * KDIM];   // fp16(aa*tanh(kk*W))
__device__ __half g_xh[MDIM * KDIM];   // fp16(x)

// ---------------------------------------------------------------------------
__device__ __forceinline__ uint32_t smem_u32(const void* p) {
    uint32_t a;
    asm("{ .reg .u64 t; cvta.to.shared.u64 t, %1; cvt.u32.u64 %0, t; }" : "=r"(a) : "l"(p));
    return a;
}

__device__ __forceinline__ void cp_async16(uint32_t smem_dst, const void* gmem_src) {
    asm volatile("cp.async.cg.shared.global [%0], [%1], 16;" :: "r"(smem_dst), "l"(gmem_src));
}
#define CP_COMMIT() asm volatile("cp.async.commit_group;" ::: "memory")
#define CP_WAIT(n)  asm volatile("cp.async.wait_group %0;" :: "n"(n) : "memory")

__device__ __forceinline__ void ldmatrix_x4(uint32_t& r0, uint32_t& r1,
                                            uint32_t& r2, uint32_t& r3, uint32_t addr) {
    asm volatile("ldmatrix.sync.aligned.m8n8.x4.shared.b16 {%0,%1,%2,%3}, [%4];"
                 : "=r"(r0), "=r"(r1), "=r"(r2), "=r"(r3) : "r"(addr));
}

__device__ __forceinline__ void mma_f16(float d[4], const uint32_t a[4],
                                        const uint32_t b[2], const float c[4]) {
    asm volatile(
        "mma.sync.aligned.m16n8k16.row.col.f32.f16.f16.f32 "
        "{%0,%1,%2,%3}, {%4,%5,%6,%7}, {%8,%9}, {%10,%11,%12,%13};"
        : "=f"(d[0]), "=f"(d[1]), "=f"(d[2]), "=f"(d[3])
        : "r"(a[0]), "r"(a[1]), "r"(a[2]), "r"(a[3]),
          "r"(b[0]), "r"(b[1]),
          "f"(c[0]), "f"(c[1]), "f"(c[2]), "f"(c[3]));
}

// ---------------------------------------------------------------------------
// Fused prep: blocks [0, W_PREP_BLOCKS) convert W (tanh.approx), the rest X.
// 16 floats -> 16 halves per thread (MLP=4).
// ---------------------------------------------------------------------------
__device__ __forceinline__ uint32_t pack2(float lo, float hi) {
    __half2 h = __floats2half2_rn(lo, hi);
    return *reinterpret_cast<uint32_t*>(&h);
}

__device__ __forceinline__ float tanh_fast(float v) {
    float r;
    asm("tanh.approx.f32 %0, %1;" : "=f"(r) : "f"(v));
    return r;
}

__global__ void __launch_bounds__(256) prep_all(const float4* __restrict__ w,
                                                const float4* __restrict__ x,
                                                const float* __restrict__ kk,
                                                const float* __restrict__ aa) {
    if (blockIdx.x < W_PREP_BLOCKS) {
        int i = blockIdx.x * 256 + threadIdx.x;
        float k = *kk, a = *aa;
        float4 v0 = w[4 * i], v1 = w[4 * i + 1], v2 = w[4 * i + 2], v3 = w[4 * i + 3];
        uint4 o0, o1;
        o0.x = pack2(a * tanh_fast(k * v0.x), a * tanh_fast(k * v0.y));
        o0.y = pack2(a * tanh_fast(k * v0.z), a * tanh_fast(k * v0.w));
        o0.z = pack2(a * tanh_fast(k * v1.x), a * tanh_fast(k * v1.y));
        o0.w = pack2(a * tanh_fast(k * v1.z), a * tanh_fast(k * v1.w));
        o1.x = pack2(a * tanh_fast(k * v2.x), a * tanh_fast(k * v2.y));
        o1.y = pack2(a * tanh_fast(k * v2.z), a * tanh_fast(k * v2.w));
        o1.z = pack2(a * tanh_fast(k * v3.x), a * tanh_fast(k * v3.y));
        o1.w = pack2(a * tanh_fast(k * v3.z), a * tanh_fast(k * v3.w));
        reinterpret_cast<uint4*>(g_wh)[2 * i] = o0;
        reinterpret_cast<uint4*>(g_wh)[2 * i + 1] = o1;
    } else {
        int i = (blockIdx.x - W_PREP_BLOCKS) * 256 + threadIdx.x;
        float4 v0 = x[4 * i], v1 = x[4 * i + 1], v2 = x[4 * i + 2], v3 = x[4 * i + 3];
        uint4 o0, o1;
        o0.x = pack2(v0.x, v0.y);  o0.y = pack2(v0.z, v0.w);
        o0.z = pack2(v1.x, v1.y);  o0.w = pack2(v1.z, v1.w);
        o1.x = pack2(v2.x, v2.y);  o1.y = pack2(v2.z, v2.w);
        o1.z = pack2(v3.x, v3.y);  o1.w = pack2(v3.z, v3.w);
        reinterpret_cast<uint4*>(g_xh)[2 * i] = o0;
        reinterpret_cast<uint4*>(g_xh)[2 * i + 1] = o1;
    }
}

// ---------------------------------------------------------------------------
// SMEM: rows of 64 halves (128B = 8 x 16B granules), SW128 swizzle:
// granule c of row r stored at slot (c ^ (r&7)).
// Load one 64-K stage: A 128x64h + B 128x64h. 2048 granules / 128 thr = 16 ea.
// ---------------------------------------------------------------------------
__device__ __forceinline__ void load_stage(const __half* __restrict__ xh,
                                           const __half* __restrict__ wh,
                                           int m0, int n0, int k0,
                                           uint32_t sdst, int tid) {
#pragma unroll
    for (int i = 0; i < 8; i++) {                 // A: 1024 granules
        int g = tid + i * 128;
        int row = g >> 3, c = g & 7;
        cp_async16(sdst + row * 128 + ((c ^ (row & 7)) << 4),
                   xh + (size_t)(m0 + row) * KDIM + k0 + c * 8);
    }
#pragma unroll
    for (int i = 0; i < 8; i++) {                 // B: 1024 granules
        int g = tid + i * 128;
        int row = g >> 3, c = g & 7;
        cp_async16(sdst + A_STAGE_BYTES + row * 128 + ((c ^ (row & 7)) << 4),
                   wh + (size_t)(n0 + row) * KDIM + k0 + c * 8);
    }
}

// ---------------------------------------------------------------------------
// GEMM: 4 warps (2x2), warp tile 64x64 (4 x 8 of m16n8k16), frag dbl-buffer.
// ---------------------------------------------------------------------------
__global__ void __launch_bounds__(128, 2) gemm_kernel(const float* __restrict__ bias,
                                                      float* __restrict__ out) {
    extern __shared__ char smem_raw[];
    const uint32_t sbase = smem_u32(smem_raw);

    const int tid = threadIdx.x;
    const int wid = tid >> 5;
    const int lane = tid & 31;
    const int wm = wid >> 1;          // 0..1 -> 64-row slab
    const int wn = wid & 1;           // 0..1 -> 64-col slab
    const int lr = lane >> 2;         // 0..7
    const int lc = lane & 3;          // 0..3

    // ldmatrix lane decomposition
    const int i8 = lane & 7;
    const int sel = lane >> 3;
    const int a_msel = (sel & 1) << 3;
    const int a_gsel = sel >> 1;
    const int b_nsel = (sel >> 1) << 3;
    const int b_gsel = sel & 1;
    const uint32_t aRowOff = (uint32_t)(wm * 64 + a_msel + i8) * 128;
    const uint32_t bRowOff = (uint32_t)(wn * 64 + b_nsel + i8) * 128;

    // grouped tile swizzle: 64 m-tiles x 32 n-tiles, GROUP_M = 8
    const int pid = blockIdx.x;
    const int group = pid >> 8;                   // / (8*32)
    const int rem = pid & 255;
    const int pm = (group << 3) + (rem & 7);
    const int pn = rem >> 3;
    const int m0 = pm * TM;
    const int n0 = pn * TN;

    float acc[4][8][4];
#pragma unroll
    for (int i = 0; i < 4; i++)
#pragma unroll
        for (int j = 0; j < 8; j++) {
            acc[i][j][0] = 0.f; acc[i][j][1] = 0.f;
            acc[i][j][2] = 0.f; acc[i][j][3] = 0.f;
        }

    // prologue: fill stages 0,1
#pragma unroll
    for (int s = 0; s < NSTAGES - 1; s++) {
        load_stage(g_xh, g_wh, m0, n0, s * TK, sbase + s * STAGE_BYTES, tid);
        CP_COMMIT();
    }

    uint32_t af[2][4][4];
    uint32_t bf[2][8][2];

    uint32_t curBase = sbase;                         // stage being consumed
    uint32_t ldBase = sbase + 2 * STAGE_BYTES;        // stage being loaded
    const uint32_t sEnd = sbase + NSTAGES * STAGE_BYTES;

    for (int it = 0; it < KITERS; ++it) {
        CP_WAIT(1);              // stage `it` resident (one group per iter)
        __syncthreads();

        const uint32_t aBase = curBase;
        const uint32_t bBase = curBase + A_STAGE_BYTES;

        // head: kq0 frags (buf0) + kq1 frags (buf1) -- 16 ldmatrix, no LDGSTS
#pragma unroll
        for (int b = 0; b < 2; b++) {
            const int ga = 2 * b + a_gsel;
            const int gb = 2 * b + b_gsel;
#pragma unroll
            for (int ms = 0; ms < 4; ms++)
                ldmatrix_x4(af[b][ms][0], af[b][ms][1], af[b][ms][2], af[b][ms][3],
                            aBase + aRowOff + ms * 2048 + ((ga ^ i8) << 4));
#pragma unroll
            for (int nsp = 0; nsp < 4; nsp++)
                ldmatrix_x4(bf[b][2 * nsp][0], bf[b][2 * nsp][1],
                            bf[b][2 * nsp + 1][0], bf[b][2 * nsp + 1][1],
                            bBase + bRowOff + nsp * 2048 + ((gb ^ i8) << 4));
        }

        // kq0 MMA burst (tensor pipe starts ~70cyc after barrier)
#pragma unroll
        for (int ms = 0; ms < 4; ms++)
#pragma unroll
            for (int ns = 0; ns < 8; ns++)
                mma_f16(acc[ms][ns], af[0][ms], bf[0][ns], acc[ms][ns]);

        // whole gmem burst for stage it+2, under the MMA shadow
        const int jt = it + NSTAGES - 1;
        if (jt < KITERS)
            load_stage(g_xh, g_wh, m0, n0, jt * TK, ldBase, tid);
        CP_COMMIT();             // always commit: CP_WAIT(1) stays valid

        // kq1..3 with frag double-buffer (kq2->buf0, kq3->buf1)
#pragma unroll
        for (int kq = 1; kq < 4; kq++) {
            const int cur = kq & 1, nxt = cur ^ 1;
            if (kq < 3) {
                const int ga = 2 * (kq + 1) + a_gsel;
                const int gb = 2 * (kq + 1) + b_gsel;
#pragma unroll
                for (int ms = 0; ms < 4; ms++)
                    ldmatrix_x4(af[nxt][ms][0], af[nxt][ms][1],
                                af[nxt][ms][2], af[nxt][ms][3],
                                aBase + aRowOff + ms * 2048 + ((ga ^ i8) << 4));
#pragma unroll
                for (int nsp = 0; nsp < 4; nsp++)
                    ldmatrix_x4(bf[nxt][2 * nsp][0], bf[nxt][2 * nsp][1],
                                bf[nxt][2 * nsp + 1][0], bf[nxt][2 * nsp + 1][1],
                                bBase + bRowOff + nsp * 2048 + ((gb ^ i8) << 4));
            }
#pragma unroll
            for (int ms = 0; ms < 4; ms++)
#pragma unroll
                for (int ns = 0; ns < 8; ns++)
                    mma_f16(acc[ms][ns], af[cur][ms], bf[cur][ns], acc[ms][ns]);
        }

        // rotate stage bases (no modulo)
        curBase += STAGE_BYTES;  if (curBase == sEnd) curBase = sbase;
        ldBase  += STAGE_BYTES;  if (ldBase  == sEnd) ldBase  = sbase;
    }

    // epilogue: c0,c1 at (row, 2*lc), c2,c3 at (row+8, 2*lc)
#pragma unroll
    for (int ms = 0; ms < 4; ms++) {
        const int rg = m0 + wm * 64 + ms * 16 + lr;
        float* o0 = out + (size_t)rg * NDIM;
        float* o1 = out + (size_t)(rg + 8) * NDIM;
#pragma unroll
        for (int ns = 0; ns < 8; ns++) {
            const int cg = n0 + wn * 64 + ns * 8 + 2 * lc;
            const float2 bv = *reinterpret_cast<const float2*>(bias + cg);
            float2 v0, v1;
            v0.x = acc[ms][ns][0] + bv.x;  v0.y = acc[ms][ns][1] + bv.y;
            v1.x = acc[ms][ns][2] + bv.x;  v1.y = acc[ms][ns][3] + bv.y;
            *reinterpret_cast<float2*>(o0 + cg) = v0;
            *reinterpret_cast<float2*>(o1 + cg) = v1;
        }
    }
}

// ---------------------------------------------------------------------------
extern "C" void kernel_launch(void* const* d_in, const int* in_sizes, int n_in,
                              void* d_out, int out_size) {
    const float* x = (const float*)d_in[0];      // [4,2048,4096]
    const float* w = (const float*)d_in[1];      // [4096,4096]
    const float* bias = (const float*)d_in[2];   // [4096]
    const float* kk = (const float*)d_in[3];
    const float* aa = (const float*)d_in[4];
    float* out = (float*)d_out;                  // [4,2048,4096]

    prep_all<<<W_PREP_BLOCKS + X_PREP_BLOCKS, 256>>>((const float4*)w,
                                                     (const float4*)x, kk, aa);

    cudaFuncSetAttribute(gemm_kernel, cudaFuncAttributeMaxDynamicSharedMemorySize, SMEM_BYTES);
    gemm_kernel<<<(MDIM / TM) * (NDIM / TN), 128, SMEM_BYTES>>>(bias, out);
}

// round 14
// speedup vs baseline: 1.0491x; 1.0491x over previous
#include <cuda_runtime.h>
#include <cuda_fp16.h>
#include <cstdint>
#include <math.h>

// ============================================================================
// BinaryLinear: y[8192,4096] = x[8192,4096] @ (aa*tanh(kk*W))^T + bias
// fp16 mma.sync.m16n8k16 register GEMM (fp32 acc), ldmatrix.x4, frag dbl-buffer.
// CTA 128x128, 4 warps (2x2), warp tile 64x64, 3-stage cp.async, TK=64 halves.
// 2 CTAs/SM; SW128 swizzle; stage-pointer rotation. R12 mainloop ordering
// (frozen). R14: odd CTAs skewed ~1200cyc to anti-phase co-resident CTAs.
// ============================================================================

#define MDIM 8192
#define NDIM 4096
#define KDIM 4096

#define TM 128
#define TN 128
#define TK 64                          // halves per stage-row (128B)
#define NSTAGES 3
#define KITERS (KDIM / TK)             // 64

#define A_STAGE_BYTES (TM * TK * 2)    // 16384
#define B_STAGE_BYTES (TN * TK * 2)    // 16384
#define STAGE_BYTES (A_STAGE_BYTES + B_STAGE_BYTES)     // 32768
#define SMEM_BYTES (NSTAGES * STAGE_BYTES)              // 98304

#define W_PREP_BLOCKS (NDIM * KDIM / 4096)   // 4096 (16 elems/thread)
#define X_PREP_BLOCKS (MDIM * KDIM / 4096)   // 8192

// fp16 operands (persistent scratch)
__device__ __half g_wh[NDIM * KDIM];   // fp16(aa*tanh(kk*W))
__device__ __half g_xh[MDIM * KDIM];   // fp16(x)

// ---------------------------------------------------------------------------
__device__ __forceinline__ uint32_t smem_u32(const void* p) {
    uint32_t a;
    asm("{ .reg .u64 t; cvta.to.shared.u64 t, %1; cvt.u32.u64 %0, t; }" : "=r"(a) : "l"(p));
    return a;
}

__device__ __forceinline__ void cp_async16(uint32_t smem_dst, const void* gmem_src) {
    asm volatile("cp.async.cg.shared.global [%0], [%1], 16;" :: "r"(smem_dst), "l"(gmem_src));
}
#define CP_COMMIT() asm volatile("cp.async.commit_group;" ::: "memory")
#define CP_WAIT(n)  asm volatile("cp.async.wait_group %0;" :: "n"(n) : "memory")

__device__ __forceinline__ void ldmatrix_x4(uint32_t& r0, uint32_t& r1,
                                            uint32_t& r2, uint32_t& r3, uint32_t addr) {
    asm volatile("ldmatrix.sync.aligned.m8n8.x4.shared.b16 {%0,%1,%2,%3}, [%4];"
                 : "=r"(r0), "=r"(r1), "=r"(r2), "=r"(r3) : "r"(addr));
}

__device__ __forceinline__ void mma_f16(float d[4], const uint32_t a[4],
                                        const uint32_t b[2], const float c[4]) {
    asm volatile(
        "mma.sync.aligned.m16n8k16.row.col.f32.f16.f16.f32 "
        "{%0,%1,%2,%3}, {%4,%5,%6,%7}, {%8,%9}, {%10,%11,%12,%13};"
        : "=f"(d[0]), "=f"(d[1]), "=f"(d[2]), "=f"(d[3])
        : "r"(a[0]), "r"(a[1]), "r"(a[2]), "r"(a[3]),
          "r"(b[0]), "r"(b[1]),
          "f"(c[0]), "f"(c[1]), "f"(c[2]), "f"(c[3]));
}

// ---------------------------------------------------------------------------
// Fused prep: blocks [0, W_PREP_BLOCKS) convert W (tanh.approx), the rest X.
// ---------------------------------------------------------------------------
__device__ __forceinline__ uint32_t pack2(float lo, float hi) {
    __half2 h = __floats2half2_rn(lo, hi);
    return *reinterpret_cast<uint32_t*>(&h);
}

__device__ __forceinline__ float tanh_fast(float v) {
    float r;
    asm("tanh.approx.f32 %0, %1;" : "=f"(r) : "f"(v));
    return r;
}

__global__ void __launch_bounds__(256) prep_all(const float4* __restrict__ w,
                                                const float4* __restrict__ x,
                                                const float* __restrict__ kk,
                                                const float* __restrict__ aa) {
    if (blockIdx.x < W_PREP_BLOCKS) {
        int i = blockIdx.x * 256 + threadIdx.x;
        float k = *kk, a = *aa;
        float4 v0 = w[4 * i], v1 = w[4 * i + 1], v2 = w[4 * i + 2], v3 = w[4 * i + 3];
        uint4 o0, o1;
        o0.x = pack2(a * tanh_fast(k * v0.x), a * tanh_fast(k * v0.y));
        o0.y = pack2(a * tanh_fast(k * v0.z), a * tanh_fast(k * v0.w));
        o0.z = pack2(a * tanh_fast(k * v1.x), a * tanh_fast(k * v1.y));
        o0.w = pack2(a * tanh_fast(k * v1.z), a * tanh_fast(k * v1.w));
        o1.x = pack2(a * tanh_fast(k * v2.x), a * tanh_fast(k * v2.y));
        o1.y = pack2(a * tanh_fast(k * v2.z), a * tanh_fast(k * v2.w));
        o1.z = pack2(a * tanh_fast(k * v3.x), a * tanh_fast(k * v3.y));
        o1.w = pack2(a * tanh_fast(k * v3.z), a * tanh_fast(k * v3.w));
        reinterpret_cast<uint4*>(g_wh)[2 * i] = o0;
        reinterpret_cast<uint4*>(g_wh)[2 * i + 1] = o1;
    } else {
        int i = (blockIdx.x - W_PREP_BLOCKS) * 256 + threadIdx.x;
        float4 v0 = x[4 * i], v1 = x[4 * i + 1], v2 = x[4 * i + 2], v3 = x[4 * i + 3];
        uint4 o0, o1;
        o0.x = pack2(v0.x, v0.y);  o0.y = pack2(v0.z, v0.w);
        o0.z = pack2(v1.x, v1.y);  o0.w = pack2(v1.z, v1.w);
        o1.x = pack2(v2.x, v2.y);  o1.y = pack2(v2.z, v2.w);
        o1.z = pack2(v3.x, v3.y);  o1.w = pack2(v3.z, v3.w);
        reinterpret_cast<uint4*>(g_xh)[2 * i] = o0;
        reinterpret_cast<uint4*>(g_xh)[2 * i + 1] = o1;
    }
}

// ---------------------------------------------------------------------------
// SMEM: rows of 64 halves (128B = 8 x 16B granules), SW128 swizzle:
// granule c of row r stored at slot (c ^ (r&7)).
// Load one 64-K stage: A 128x64h + B 128x64h. 2048 granules / 128 thr = 16 ea.
// ---------------------------------------------------------------------------
__device__ __forceinline__ void load_stage(const __half* __restrict__ xh,
                                           const __half* __restrict__ wh,
                                           int m0, int n0, int k0,
                                           uint32_t sdst, int tid) {
#pragma unroll
    for (int i = 0; i < 8; i++) {                 // A: 1024 granules
        int g = tid + i * 128;
        int row = g >> 3, c = g & 7;
        cp_async16(sdst + row * 128 + ((c ^ (row & 7)) << 4),
                   xh + (size_t)(m0 + row) * KDIM + k0 + c * 8);
    }
#pragma unroll
    for (int i = 0; i < 8; i++) {                 // B: 1024 granules
        int g = tid + i * 128;
        int row = g >> 3, c = g & 7;
        cp_async16(sdst + A_STAGE_BYTES + row * 128 + ((c ^ (row & 7)) << 4),
                   wh + (size_t)(n0 + row) * KDIM + k0 + c * 8);
    }
}

// ---------------------------------------------------------------------------
// GEMM: 4 warps (2x2), warp tile 64x64 (4 x 8 of m16n8k16), frag dbl-buffer.
// ---------------------------------------------------------------------------
__global__ void __launch_bounds__(128, 2) gemm_kernel(const float* __restrict__ bias,
                                                      float* __restrict__ out) {
    extern __shared__ char smem_raw[];
    const uint32_t sbase = smem_u32(smem_raw);

    const int tid = threadIdx.x;
    const int wid = tid >> 5;
    const int lane = tid & 31;
    const int wm = wid >> 1;          // 0..1 -> 64-row slab
    const int wn = wid & 1;           // 0..1 -> 64-col slab
    const int lr = lane >> 2;         // 0..7
    const int lc = lane & 3;          // 0..3

    // ldmatrix lane decomposition
    const int i8 = lane & 7;
    const int sel = lane >> 3;
    const int a_msel = (sel & 1) << 3;
    const int a_gsel = sel >> 1;
    const int b_nsel = (sel >> 1) << 3;
    const int b_gsel = sel & 1;
    const uint32_t aRowOff = (uint32_t)(wm * 64 + a_msel + i8) * 128;
    const uint32_t bRowOff = (uint32_t)(wn * 64 + b_nsel + i8) * 128;

    // grouped tile swizzle: 64 m-tiles x 32 n-tiles, GROUP_M = 8
    const int pid = blockIdx.x;
    const int group = pid >> 8;                   // / (8*32)
    const int rem = pid & 255;
    const int pm = (group << 3) + (rem & 7);
    const int pn = rem >> 3;
    const int m0 = pm * TM;
    const int n0 = pn * TN;

    float acc[4][8][4];
#pragma unroll
    for (int i = 0; i < 4; i++)
#pragma unroll
        for (int j = 0; j < 8; j++) {
            acc[i][j][0] = 0.f; acc[i][j][1] = 0.f;
            acc[i][j][2] = 0.f; acc[i][j][3] = 0.f;
        }

    // prologue: fill stages 0,1
#pragma unroll
    for (int s = 0; s < NSTAGES - 1; s++) {
        load_stage(g_xh, g_wh, m0, n0, s * TK, sbase + s * STAGE_BYTES, tid);
        CP_COMMIT();
    }

    // R14: anti-phase skew — odd CTAs burn ~1200cyc (dependent-FFMA chain)
    // while their prologue cp.async is in flight. De-phases the two
    // co-resident CTAs so one computes while the other is in its
    // barrier/frag-load window. Deterministic (fixed-length chain).
    if (pid & 1) {
        float v = (float)tid * 1.0e-12f;
#pragma unroll 1
        for (int i = 0; i < 60; i++) {
            v = fmaf(v, 1.0000001f, 1.0e-9f);
            v = fmaf(v, 1.0000001f, 1.0e-9f);
            v = fmaf(v, 1.0000001f, 1.0e-9f);
            v = fmaf(v, 1.0000001f, 1.0e-9f);
            v = fmaf(v, 1.0000001f, 1.0e-9f);
        }
        asm volatile("" :: "f"(v));   // keep the chain alive
    }

    uint32_t af[2][4][4];
    uint32_t bf[2][8][2];

    uint32_t curBase = sbase;                         // stage being consumed
    uint32_t ldBase = sbase + 2 * STAGE_BYTES;        // stage being loaded
    const uint32_t sEnd = sbase + NSTAGES * STAGE_BYTES;

    for (int it = 0; it < KITERS; ++it) {
        CP_WAIT(1);              // stage `it` resident (one group per iter)
        __syncthreads();

        const uint32_t aBase = curBase;
        const uint32_t bBase = curBase + A_STAGE_BYTES;

        // frag load for kq=0 into buffer 0 (starts immediately post-barrier)
        {
            const int ga = a_gsel, gb = b_gsel;
#pragma unroll
            for (int ms = 0; ms < 4; ms++)
                ldmatrix_x4(af[0][ms][0], af[0][ms][1], af[0][ms][2], af[0][ms][3],
                            aBase + aRowOff + ms * 2048 + ((ga ^ i8) << 4));
#pragma unroll
            for (int nsp = 0; nsp < 4; nsp++)
                ldmatrix_x4(bf[0][2 * nsp][0], bf[0][2 * nsp][1],
                            bf[0][2 * nsp + 1][0], bf[0][2 * nsp + 1][1],
                            bBase + bRowOff + nsp * 2048 + ((gb ^ i8) << 4));
        }

        // front-batched gmem burst for stage it+2 (R12 ordering, frozen)
        const int jt = it + NSTAGES - 1;
        if (jt < KITERS)
            load_stage(g_xh, g_wh, m0, n0, jt * TK, ldBase, tid);
        CP_COMMIT();             // always commit: CP_WAIT(1) stays valid

#pragma unroll
        for (int kq = 0; kq < 4; kq++) {          // 4 x k16 steps
            const int cur = kq & 1, nxt = cur ^ 1;
            if (kq < 3) {                         // prefetch kq+1 frags
                const int ga = 2 * (kq + 1) + a_gsel;
                const int gb = 2 * (kq + 1) + b_gsel;
#pragma unroll
                for (int ms = 0; ms < 4; ms++)
                    ldmatrix_x4(af[nxt][ms][0], af[nxt][ms][1],
                                af[nxt][ms][2], af[nxt][ms][3],
                                aBase + aRowOff + ms * 2048 + ((ga ^ i8) << 4));
#pragma unroll
                for (int nsp = 0; nsp < 4; nsp++)
                    ldmatrix_x4(bf[nxt][2 * nsp][0], bf[nxt][2 * nsp][1],
                                bf[nxt][2 * nsp + 1][0], bf[nxt][2 * nsp + 1][1],
                                bBase + bRowOff + nsp * 2048 + ((gb ^ i8) << 4));
            }
#pragma unroll
            for (int ms = 0; ms < 4; ms++)
#pragma unroll
                for (int ns = 0; ns < 8; ns++)
                    mma_f16(acc[ms][ns], af[cur][ms], bf[cur][ns], acc[ms][ns]);
        }

        // rotate stage bases (no modulo)
        curBase += STAGE_BYTES;  if (curBase == sEnd) curBase = sbase;
        ldBase  += STAGE_BYTES;  if (ldBase  == sEnd) ldBase  = sbase;
    }

    // epilogue: c0,c1 at (row, 2*lc), c2,c3 at (row+8, 2*lc)
#pragma unroll
    for (int ms = 0; ms < 4; ms++) {
        const int rg = m0 + wm * 64 + ms * 16 + lr;
        float* o0 = out + (size_t)rg * NDIM;
        float* o1 = out + (size_t)(rg + 8) * NDIM;
#pragma unroll
        for (int ns = 0; ns < 8; ns++) {
            const int cg = n0 + wn * 64 + ns * 8 + 2 * lc;
            const float2 bv = *reinterpret_cast<const float2*>(bias + cg);
            float2 v0, v1;
            v0.x = acc[ms][ns][0] + bv.x;  v0.y = acc[ms][ns][1] + bv.y;
            v1.x = acc[ms][ns][2] + bv.x;  v1.y = acc[ms][ns][3] + bv.y;
            *reinterpret_cast<float2*>(o0 + cg) = v0;
            *reinterpret_cast<float2*>(o1 + cg) = v1;
        }
    }
}

// ---------------------------------------------------------------------------
extern "C" void kernel_launch(void* const* d_in, const int* in_sizes, int n_in,
                              void* d_out, int out_size) {
    const float* x = (const float*)d_in[0];      // [4,2048,4096]
    const float* w = (const float*)d_in[1];      // [4096,4096]
    const float* bias = (const float*)d_in[2];   // [4096]
    const float* kk = (const float*)d_in[3];
    const float* aa = (const float*)d_in[4];
    float* out = (float*)d_out;                  // [4,2048,4096]

    prep_all<<<W_PREP_BLOCKS + X_PREP_BLOCKS, 256>>>((const float4*)w,
                                                     (const float4*)x, kk, aa);

    cudaFuncSetAttribute(gemm_kernel, cudaFuncAttributeMaxDynamicSharedMemorySize, SMEM_BYTES);
    gemm_kernel<<<(MDIM / TM) * (NDIM / TN), 128, SMEM_BYTES>>>(bias, out);
}

// round 15
// speedup vs baseline: 1.0746x; 1.0244x over previous
#include <cuda_runtime.h>
#include <cuda_fp16.h>
#include <cstdint>
#include <math.h>

// ============================================================================
// BinaryLinear: y[8192,4096] = x[8192,4096] @ (aa*tanh(kk*W))^T + bias
// fp16 mma.sync.m16n8k16 register GEMM (fp32 acc), ldmatrix.x4, frag dbl-buffer.
// CTA 128x128, 4 warps (2x2), warp tile 64x64, 3-stage cp.async, TK=64 halves.
// 2 CTAs/SM; SW128 swizzle; stage-pointer rotation; R12 gmem ordering (frozen).
// R15: kq0 frags of stage it+1 preloaded during iter it's kq3 (CP_WAIT(0)
//      guarantees residency) -> zero-LDSM post-barrier head.
// ============================================================================

#define MDIM 8192
#define NDIM 4096
#define KDIM 4096

#define TM 128
#define TN 128
#define TK 64                          // halves per stage-row (128B)
#define NSTAGES 3
#define KITERS (KDIM / TK)             // 64

#define A_STAGE_BYTES (TM * TK * 2)    // 16384
#define B_STAGE_BYTES (TN * TK * 2)    // 16384
#define STAGE_BYTES (A_STAGE_BYTES + B_STAGE_BYTES)     // 32768
#define SMEM_BYTES (NSTAGES * STAGE_BYTES)              // 98304

#define W_PREP_BLOCKS (NDIM * KDIM / 4096)   // 4096 (16 elems/thread)
#define X_PREP_BLOCKS (MDIM * KDIM / 4096)   // 8192

// fp16 operands (persistent scratch)
__device__ __half g_wh[NDIM * KDIM];   // fp16(aa*tanh(kk*W))
__device__ __half g_xh[MDIM * KDIM];   // fp16(x)

// ---------------------------------------------------------------------------
__device__ __forceinline__ uint32_t smem_u32(const void* p) {
    uint32_t a;
    asm("{ .reg .u64 t; cvta.to.shared.u64 t, %1; cvt.u32.u64 %0, t; }" : "=r"(a) : "l"(p));
    return a;
}

__device__ __forceinline__ void cp_async16(uint32_t smem_dst, const void* gmem_src) {
    asm volatile("cp.async.cg.shared.global [%0], [%1], 16;" :: "r"(smem_dst), "l"(gmem_src));
}
#define CP_COMMIT() asm volatile("cp.async.commit_group;" ::: "memory")
#define CP_WAIT(n)  asm volatile("cp.async.wait_group %0;" :: "n"(n) : "memory")

__device__ __forceinline__ void ldmatrix_x4(uint32_t& r0, uint32_t& r1,
                                            uint32_t& r2, uint32_t& r3, uint32_t addr) {
    asm volatile("ldmatrix.sync.aligned.m8n8.x4.shared.b16 {%0,%1,%2,%3}, [%4];"
                 : "=r"(r0), "=r"(r1), "=r"(r2), "=r"(r3) : "r"(addr));
}

__device__ __forceinline__ void mma_f16(float d[4], const uint32_t a[4],
                                        const uint32_t b[2], const float c[4]) {
    asm volatile(
        "mma.sync.aligned.m16n8k16.row.col.f32.f16.f16.f32 "
        "{%0,%1,%2,%3}, {%4,%5,%6,%7}, {%8,%9}, {%10,%11,%12,%13};"
        : "=f"(d[0]), "=f"(d[1]), "=f"(d[2]), "=f"(d[3])
        : "r"(a[0]), "r"(a[1]), "r"(a[2]), "r"(a[3]),
          "r"(b[0]), "r"(b[1]),
          "f"(c[0]), "f"(c[1]), "f"(c[2]), "f"(c[3]));
}

// ---------------------------------------------------------------------------
// Fused prep: blocks [0, W_PREP_BLOCKS) convert W (tanh.approx), the rest X.
// ---------------------------------------------------------------------------
__device__ __forceinline__ uint32_t pack2(float lo, float hi) {
    __half2 h = __floats2half2_rn(lo, hi);
    return *reinterpret_cast<uint32_t*>(&h);
}

__device__ __forceinline__ float tanh_fast(float v) {
    float r;
    asm("tanh.approx.f32 %0, %1;" : "=f"(r) : "f"(v));
    return r;
}

__global__ void __launch_bounds__(256) prep_all(const float4* __restrict__ w,
                                                const float4* __restrict__ x,
                                                const float* __restrict__ kk,
                                                const float* __restrict__ aa) {
    if (blockIdx.x < W_PREP_BLOCKS) {
        int i = blockIdx.x * 256 + threadIdx.x;
        float k = *kk, a = *aa;
        float4 v0 = w[4 * i], v1 = w[4 * i + 1], v2 = w[4 * i + 2], v3 = w[4 * i + 3];
        uint4 o0, o1;
        o0.x = pack2(a * tanh_fast(k * v0.x), a * tanh_fast(k * v0.y));
        o0.y = pack2(a * tanh_fast(k * v0.z), a * tanh_fast(k * v0.w));
        o0.z = pack2(a * tanh_fast(k * v1.x), a * tanh_fast(k * v1.y));
        o0.w = pack2(a * tanh_fast(k * v1.z), a * tanh_fast(k * v1.w));
        o1.x = pack2(a * tanh_fast(k * v2.x), a * tanh_fast(k * v2.y));
        o1.y = pack2(a * tanh_fast(k * v2.z), a * tanh_fast(k * v2.w));
        o1.z = pack2(a * tanh_fast(k * v3.x), a * tanh_fast(k * v3.y));
        o1.w = pack2(a * tanh_fast(k * v3.z), a * tanh_fast(k * v3.w));
        reinterpret_cast<uint4*>(g_wh)[2 * i] = o0;
        reinterpret_cast<uint4*>(g_wh)[2 * i + 1] = o1;
    } else {
        int i = (blockIdx.x - W_PREP_BLOCKS) * 256 + threadIdx.x;
        float4 v0 = x[4 * i], v1 = x[4 * i + 1], v2 = x[4 * i + 2], v3 = x[4 * i + 3];
        uint4 o0, o1;
        o0.x = pack2(v0.x, v0.y);  o0.y = pack2(v0.z, v0.w);
        o0.z = pack2(v1.x, v1.y);  o0.w = pack2(v1.z, v1.w);
        o1.x = pack2(v2.x, v2.y);  o1.y = pack2(v2.z, v2.w);
        o1.z = pack2(v3.x, v3.y);  o1.w = pack2(v3.z, v3.w);
        reinterpret_cast<uint4*>(g_xh)[2 * i] = o0;
        reinterpret_cast<uint4*>(g_xh)[2 * i + 1] = o1;
    }
}

// ---------------------------------------------------------------------------
// SMEM: rows of 64 halves (128B = 8 x 16B granules), SW128 swizzle:
// granule c of row r stored at slot (c ^ (r&7)).
// Load one 64-K stage: A 128x64h + B 128x64h. 2048 granules / 128 thr = 16 ea.
// ---------------------------------------------------------------------------
__device__ __forceinline__ void load_stage(const __half* __restrict__ xh,
                                           const __half* __restrict__ wh,
                                           int m0, int n0, int k0,
                                           uint32_t sdst, int tid) {
#pragma unroll
    for (int i = 0; i < 8; i++) {                 // A: 1024 granules
        int g = tid + i * 128;
        int row = g >> 3, c = g & 7;
        cp_async16(sdst + row * 128 + ((c ^ (row & 7)) << 4),
                   xh + (size_t)(m0 + row) * KDIM + k0 + c * 8);
    }
#pragma unroll
    for (int i = 0; i < 8; i++) {                 // B: 1024 granules
        int g = tid + i * 128;
        int row = g >> 3, c = g & 7;
        cp_async16(sdst + A_STAGE_BYTES + row * 128 + ((c ^ (row & 7)) << 4),
                   wh + (size_t)(n0 + row) * KDIM + k0 + c * 8);
    }
}

// ---------------------------------------------------------------------------
// GEMM: 4 warps (2x2), warp tile 64x64 (4 x 8 of m16n8k16), frag dbl-buffer
// with cross-stage kq0 preload.
// ---------------------------------------------------------------------------
__global__ void __launch_bounds__(128, 2) gemm_kernel(const float* __restrict__ bias,
                                                      float* __restrict__ out) {
    extern __shared__ char smem_raw[];
    const uint32_t sbase = smem_u32(smem_raw);

    const int tid = threadIdx.x;
    const int wid = tid >> 5;
    const int lane = tid & 31;
    const int wm = wid >> 1;          // 0..1 -> 64-row slab
    const int wn = wid & 1;           // 0..1 -> 64-col slab
    const int lr = lane >> 2;         // 0..7
    const int lc = lane & 3;          // 0..3

    // ldmatrix lane decomposition
    const int i8 = lane & 7;
    const int sel = lane >> 3;
    const int a_msel = (sel & 1) << 3;
    const int a_gsel = sel >> 1;
    const int b_nsel = (sel >> 1) << 3;
    const int b_gsel = sel & 1;
    const uint32_t aRowOff = (uint32_t)(wm * 64 + a_msel + i8) * 128;
    const uint32_t bRowOff = (uint32_t)(wn * 64 + b_nsel + i8) * 128;

    // grouped tile swizzle: 64 m-tiles x 32 n-tiles, GROUP_M = 8
    const int pid = blockIdx.x;
    const int group = pid >> 8;                   // / (8*32)
    const int rem = pid & 255;
    const int pm = (group << 3) + (rem & 7);
    const int pn = rem >> 3;
    const int m0 = pm * TM;
    const int n0 = pn * TN;

    float acc[4][8][4];
#pragma unroll
    for (int i = 0; i < 4; i++)
#pragma unroll
        for (int j = 0; j < 8; j++) {
            acc[i][j][0] = 0.f; acc[i][j][1] = 0.f;
            acc[i][j][2] = 0.f; acc[i][j][3] = 0.f;
        }

    // prologue: fill stages 0,1
#pragma unroll
    for (int s = 0; s < NSTAGES - 1; s++) {
        load_stage(g_xh, g_wh, m0, n0, s * TK, sbase + s * STAGE_BYTES, tid);
        CP_COMMIT();
    }

    uint32_t af[2][4][4];
    uint32_t bf[2][8][2];

    // preload kq0 frags of stage 0 (before mainloop)
    CP_WAIT(1);                  // stage 0 resident
    __syncthreads();
    {
        const uint32_t aB = sbase, bB = sbase + A_STAGE_BYTES;
        const int ga = a_gsel, gb = b_gsel;
#pragma unroll
        for (int ms = 0; ms < 4; ms++)
            ldmatrix_x4(af[0][ms][0], af[0][ms][1], af[0][ms][2], af[0][ms][3],
                        aB + aRowOff + ms * 2048 + ((ga ^ i8) << 4));
#pragma unroll
        for (int nsp = 0; nsp < 4; nsp++)
            ldmatrix_x4(bf[0][2 * nsp][0], bf[0][2 * nsp][1],
                        bf[0][2 * nsp + 1][0], bf[0][2 * nsp + 1][1],
                        bB + bRowOff + nsp * 2048 + ((gb ^ i8) << 4));
    }

    uint32_t curBase = sbase;                         // stage being consumed
    uint32_t ldBase = sbase + 2 * STAGE_BYTES;        // stage being loaded
    const uint32_t sEnd = sbase + NSTAGES * STAGE_BYTES;

    for (int it = 0; it < KITERS; ++it) {
        CP_WAIT(0);              // stages it AND it+1 resident
        __syncthreads();

        const uint32_t aBase = curBase;
        const uint32_t bBase = curBase + A_STAGE_BYTES;
        uint32_t nBase = curBase + STAGE_BYTES;
        if (nBase == sEnd) nBase = sbase;             // stage it+1 slot

        // front-batched gmem burst for stage it+2 (R12 ordering, frozen)
        const int jt = it + NSTAGES - 1;
        if (jt < KITERS)
            load_stage(g_xh, g_wh, m0, n0, jt * TK, ldBase, tid);
        CP_COMMIT();             // always commit: CP_WAIT(0) handles the rest

#pragma unroll
        for (int kq = 0; kq < 4; kq++) {          // 4 x k16 steps
            const int cur = kq & 1, nxt = cur ^ 1;
            if (kq < 3) {                         // prefetch kq+1 frags (this stage)
                const int ga = 2 * (kq + 1) + a_gsel;
                const int gb = 2 * (kq + 1) + b_gsel;
#pragma unroll
                for (int ms = 0; ms < 4; ms++)
                    ldmatrix_x4(af[nxt][ms][0], af[nxt][ms][1],
                                af[nxt][ms][2], af[nxt][ms][3],
                                aBase + aRowOff + ms * 2048 + ((ga ^ i8) << 4));
#pragma unroll
                for (int nsp = 0; nsp < 4; nsp++)
                    ldmatrix_x4(bf[nxt][2 * nsp][0], bf[nxt][2 * nsp][1],
                                bf[nxt][2 * nsp + 1][0], bf[nxt][2 * nsp + 1][1],
                                bBase + bRowOff + nsp * 2048 + ((gb ^ i8) << 4));
            } else {                              // kq==3: preload NEXT stage's kq0
                const int ga = a_gsel, gb = b_gsel;
                const uint32_t aN = nBase, bN = nBase + A_STAGE_BYTES;
#pragma unroll
                for (int ms = 0; ms < 4; ms++)
                    ldmatrix_x4(af[nxt][ms][0], af[nxt][ms][1],
                                af[nxt][ms][2], af[nxt][ms][3],
                                aN + aRowOff + ms * 2048 + ((ga ^ i8) << 4));
#pragma unroll
                for (int nsp = 0; nsp < 4; nsp++)
                    ldmatrix_x4(bf[nxt][2 * nsp][0], bf[nxt][2 * nsp][1],
                                bf[nxt][2 * nsp + 1][0], bf[nxt][2 * nsp + 1][1],
                                bN + bRowOff + nsp * 2048 + ((gb ^ i8) << 4));
            }
#pragma unroll
            for (int ms = 0; ms < 4; ms++)
#pragma unroll
                for (int ns = 0; ns < 8; ns++)
                    mma_f16(acc[ms][ns], af[cur][ms], bf[cur][ns], acc[ms][ns]);
        }

        // rotate stage bases (no modulo)
        curBase += STAGE_BYTES;  if (curBase == sEnd) curBase = sbase;
        ldBase  += STAGE_BYTES;  if (ldBase  == sEnd) ldBase  = sbase;
    }

    // epilogue: c0,c1 at (row, 2*lc), c2,c3 at (row+8, 2*lc)
#pragma unroll
    for (int ms = 0; ms < 4; ms++) {
        const int rg = m0 + wm * 64 + ms * 16 + lr;
        float* o0 = out + (size_t)rg * NDIM;
        float* o1 = out + (size_t)(rg + 8) * NDIM;
#pragma unroll
        for (int ns = 0; ns < 8; ns++) {
            const int cg = n0 + wn * 64 + ns * 8 + 2 * lc;
            const float2 bv = *reinterpret_cast<const float2*>(bias + cg);
            float2 v0, v1;
            v0.x = acc[ms][ns][0] + bv.x;  v0.y = acc[ms][ns][1] + bv.y;
            v1.x = acc[ms][ns][2] + bv.x;  v1.y = acc[ms][ns][3] + bv.y;
            *reinterpret_cast<float2*>(o0 + cg) = v0;
            *reinterpret_cast<float2*>(o1 + cg) = v1;
        }
    }
}

// ---------------------------------------------------------------------------
extern "C" void kernel_launch(void* const* d_in, const int* in_sizes, int n_in,
                              void* d_out, int out_size) {
    const float* x = (const float*)d_in[0];      // [4,2048,4096]
    const float* w = (const float*)d_in[1];      // [4096,4096]
    const float* bias = (const float*)d_in[2];   // [4096]
    const float* kk = (const float*)d_in[3];
    const float* aa = (const float*)d_in[4];
    float* out = (float*)d_out;                  // [4,2048,4096]

    prep_all<<<W_PREP_BLOCKS + X_PREP_BLOCKS, 256>>>((const float4*)w,
                                                     (const float4*)x, kk, aa);

    cudaFuncSetAttribute(gemm_kernel, cudaFuncAttributeMaxDynamicSharedMemorySize, SMEM_BYTES);
    gemm_kernel<<<(MDIM / TM) * (NDIM / TN), 128, SMEM_BYTES>>>(bias, out);
}